// round 2
// baseline (speedup 1.0000x reference)
#include <cuda_runtime.h>

// Problem constants (fixed shapes from reference setup_inputs)
#define MAXN 200000
#define MAXE 6400000
#define NUM_G 1024

// ---------------- scratch (static __device__, no allocation) ----------------
__device__ int   d_cnt[MAXN];        // in-degree (excl. self loop)
__device__ int   d_cursor[MAXN];     // CSR fill cursors
__device__ int   d_offs[MAXN];       // CSR row offsets (exclusive scan of cnt)
__device__ int   d_bsum[1024];       // block sums for scan
__device__ float d_dinv[MAXN];       // deg^{-1/2} (deg incl. self loop)
__device__ int   d_src[MAXE];        // CSR source-node ids (int32)
__device__ float d_xw1[(size_t)MAXN * 16];
__device__ float d_h1 [(size_t)MAXN * 16];
__device__ float d_xw2[(size_t)MAXN * 32];
__device__ float d_gsum[NUM_G * 32];
__device__ int   d_gcnt[NUM_G];

// ---------------- init ----------------
__global__ void k_zero(int n) {
    int i = blockIdx.x * blockDim.x + threadIdx.x;
    if (i < n) { d_cnt[i] = 0; d_cursor[i] = 0; }
    if (i < NUM_G * 32) d_gsum[i] = 0.0f;
    if (i < NUM_G) d_gcnt[i] = 0;
}

// ---------------- degree count (targets = edge_index[1]) ----------------
__global__ void k_deg(const int* __restrict__ ei, int E) {
    int e = blockIdx.x * blockDim.x + threadIdx.x;
    if (e < E) {
        int c = ei[(size_t)E + e];
        atomicAdd(&d_cnt[c], 1);
    }
}

// ---------------- exclusive scan of cnt -> offs (3 kernels) ----------------
__global__ void k_scan1(int n) {
    __shared__ int s[1024];
    int tid = threadIdx.x;
    int gid = blockIdx.x * 1024 + tid;
    int v = (gid < n) ? d_cnt[gid] : 0;
    s[tid] = v;
    __syncthreads();
    for (int d = 1; d < 1024; d <<= 1) {
        int t = (tid >= d) ? s[tid - d] : 0;
        __syncthreads();
        s[tid] += t;
        __syncthreads();
    }
    if (gid < n) d_offs[gid] = s[tid] - v;       // exclusive within block
    if (tid == 1023) d_bsum[blockIdx.x] = s[1023];
}

__global__ void k_scan2(int nb) {
    __shared__ int s[1024];
    int tid = threadIdx.x;
    int v = (tid < nb) ? d_bsum[tid] : 0;
    s[tid] = v;
    __syncthreads();
    for (int d = 1; d < 1024; d <<= 1) {
        int t = (tid >= d) ? s[tid - d] : 0;
        __syncthreads();
        s[tid] += t;
        __syncthreads();
    }
    if (tid < nb) d_bsum[tid] = s[tid] - v;      // exclusive block offsets
}

__global__ void k_scan3_dinv(int n) {
    int gid = blockIdx.x * 1024 + threadIdx.x;
    if (gid < n) {
        d_offs[gid] += d_bsum[blockIdx.x];
        d_dinv[gid] = rsqrtf((float)d_cnt[gid] + 1.0f);  // +1 self loop
    }
}

// ---------------- CSR fill ----------------
__global__ void k_fill(const int* __restrict__ ei, int E) {
    int e = blockIdx.x * blockDim.x + threadIdx.x;
    if (e < E) {
        int r = ei[e];
        int c = ei[(size_t)E + e];
        int p = d_offs[c] + atomicAdd(&d_cursor[c], 1);
        d_src[p] = r;
    }
}

// ---------------- layer-1 transform: xw1 = x @ W1 (3 -> 16) ----------------
__global__ void k_xw1(const float* __restrict__ x, const float* __restrict__ W1, int n) {
    __shared__ float w[48];
    if (threadIdx.x < 48) w[threadIdx.x] = W1[threadIdx.x];
    __syncthreads();
    int i = blockIdx.x * blockDim.x + threadIdx.x;
    if (i >= n) return;
    float x0 = x[3 * (size_t)i], x1 = x[3 * (size_t)i + 1], x2 = x[3 * (size_t)i + 2];
    float* out = d_xw1 + (size_t)i * 16;
#pragma unroll
    for (int f = 0; f < 16; f++)
        out[f] = x0 * w[f] + x1 * w[16 + f] + x2 * w[32 + f];
}

// ---------------- aggregation layer 1 (F=16), warp per node ----------------
__global__ void k_agg1(const float* __restrict__ b1, int n) {
    int wnode = (blockIdx.x * blockDim.x + threadIdx.x) >> 5;
    int lane = threadIdx.x & 31;
    if (wnode >= n) return;

    float acc[16];
#pragma unroll
    for (int f = 0; f < 16; f++) acc[f] = 0.0f;

    int o = d_offs[wnode];
    int e = o + d_cnt[wnode];
    for (int k = o + lane; k < e; k += 32) {
        int j = d_src[k];
        float wt = d_dinv[j];
        const float4* row = (const float4*)(d_xw1 + (size_t)j * 16);
#pragma unroll
        for (int q = 0; q < 4; q++) {
            float4 v = row[q];
            acc[4 * q + 0] += wt * v.x;
            acc[4 * q + 1] += wt * v.y;
            acc[4 * q + 2] += wt * v.z;
            acc[4 * q + 3] += wt * v.w;
        }
    }
#pragma unroll
    for (int f = 0; f < 16; f++) {
#pragma unroll
        for (int off = 16; off; off >>= 1)
            acc[f] += __shfl_xor_sync(0xffffffffu, acc[f], off);
    }
    if (lane == 0) {
        float di = d_dinv[wnode];
        const float* self = d_xw1 + (size_t)wnode * 16;
        float* out = d_h1 + (size_t)wnode * 16;
#pragma unroll
        for (int f = 0; f < 16; f++) {
            float hv = di * (acc[f] + di * self[f]) + b1[f];
            out[f] = hv > 0.0f ? hv : 0.0f;
        }
    }
}

// ---------------- layer-2 transform: xw2 = h1 @ W2 (16 -> 32) ----------------
__global__ void k_xw2(const float* __restrict__ W2, int n) {
    __shared__ float w[512];
    for (int t = threadIdx.x; t < 512; t += blockDim.x) w[t] = W2[t];
    __syncthreads();
    int i = blockIdx.x * blockDim.x + threadIdx.x;
    if (i >= n) return;
    float h[16];
    const float4* hin = (const float4*)(d_h1 + (size_t)i * 16);
#pragma unroll
    for (int q = 0; q < 4; q++) {
        float4 v = hin[q];
        h[4 * q] = v.x; h[4 * q + 1] = v.y; h[4 * q + 2] = v.z; h[4 * q + 3] = v.w;
    }
    float* out = d_xw2 + (size_t)i * 32;
#pragma unroll
    for (int f = 0; f < 32; f++) {
        float s = 0.0f;
#pragma unroll
        for (int k = 0; k < 16; k++) s += h[k] * w[k * 32 + f];
        out[f] = s;
    }
}

// ------- aggregation layer 2 (F=32), warp per node, fused mean-pool -------
__global__ void k_agg2(const float* __restrict__ b2,
                       const int* __restrict__ batch, int n) {
    int wnode = (blockIdx.x * blockDim.x + threadIdx.x) >> 5;
    int lane = threadIdx.x & 31;
    if (wnode >= n) return;

    float acc[32];
#pragma unroll
    for (int f = 0; f < 32; f++) acc[f] = 0.0f;

    int o = d_offs[wnode];
    int e = o + d_cnt[wnode];
    for (int k = o + lane; k < e; k += 32) {
        int j = d_src[k];
        float wt = d_dinv[j];
        const float4* row = (const float4*)(d_xw2 + (size_t)j * 32);
#pragma unroll
        for (int q = 0; q < 8; q++) {
            float4 v = row[q];
            acc[4 * q + 0] += wt * v.x;
            acc[4 * q + 1] += wt * v.y;
            acc[4 * q + 2] += wt * v.z;
            acc[4 * q + 3] += wt * v.w;
        }
    }
#pragma unroll
    for (int f = 0; f < 32; f++) {
#pragma unroll
        for (int off = 16; off; off >>= 1)
            acc[f] += __shfl_xor_sync(0xffffffffu, acc[f], off);
    }
    if (lane == 0) {
        float di = d_dinv[wnode];
        const float* self = d_xw2 + (size_t)wnode * 32;
        int g = batch[wnode];
        float* gs = d_gsum + g * 32;
#pragma unroll
        for (int f = 0; f < 32; f++) {
            float hv = di * (acc[f] + di * self[f]) + b2[f];
            hv = hv > 0.0f ? hv : 0.0f;
            atomicAdd(&gs[f], hv);
        }
        atomicAdd(&d_gcnt[g], 1);
    }
}

// ---------------- mean + FC + log_softmax ----------------
__global__ void k_final(const float* __restrict__ Wfc, const float* __restrict__ bfc,
                        float* __restrict__ out) {
    int g = blockIdx.x * blockDim.x + threadIdx.x;
    if (g >= NUM_G) return;
    float c = (float)d_gcnt[g];
    float inv = 1.0f / fmaxf(c, 1.0f);
    float l0 = bfc[0], l1 = bfc[1];
    const float* gs = d_gsum + g * 32;
#pragma unroll
    for (int k = 0; k < 32; k++) {
        float m = gs[k] * inv;
        l0 += m * Wfc[k * 2 + 0];
        l1 += m * Wfc[k * 2 + 1];
    }
    float mx = fmaxf(l0, l1);
    float lse = mx + logf(expf(l0 - mx) + expf(l1 - mx));
    out[g * 2 + 0] = l0 - lse;
    out[g * 2 + 1] = l1 - lse;
}

// ---------------- launch ----------------
extern "C" void kernel_launch(void* const* d_in, const int* in_sizes, int n_in,
                              void* d_out, int out_size) {
    const float* x   = (const float*)d_in[0];
    const int*   ei  = (const int*)d_in[1];
    const int*   bat = (const int*)d_in[2];
    const float* W1  = (const float*)d_in[3];
    const float* b1  = (const float*)d_in[4];
    const float* W2  = (const float*)d_in[5];
    const float* b2  = (const float*)d_in[6];
    const float* Wfc = (const float*)d_in[7];
    const float* bfc = (const float*)d_in[8];
    float* out = (float*)d_out;

    int N = in_sizes[0] / 3;
    int E = in_sizes[1] / 2;

    int zmax = N > NUM_G * 32 ? N : NUM_G * 32;
    k_zero<<<(zmax + 255) / 256, 256>>>(N);
    k_deg<<<(E + 255) / 256, 256>>>(ei, E);

    int nb = (N + 1023) / 1024;
    k_scan1<<<nb, 1024>>>(N);
    k_scan2<<<1, 1024>>>(nb);
    k_scan3_dinv<<<nb, 1024>>>(N);

    k_fill<<<(E + 255) / 256, 256>>>(ei, E);

    k_xw1<<<(N + 255) / 256, 256>>>(x, W1, N);
    k_agg1<<<(N + 7) / 8, 256>>>(b1, N);
    k_xw2<<<(N + 255) / 256, 256>>>(W2, N);
    k_agg2<<<(N + 7) / 8, 256>>>(b2, bat, N);
    k_final<<<(NUM_G + 255) / 256, 256>>>(Wfc, bfc, out);
}

// round 3
// speedup vs baseline: 2.6868x; 2.6868x over previous
#include <cuda_runtime.h>

#define MAXN 200000
#define MAXE 6400000
#define NUM_G 1024

// ---------------- scratch ----------------
__device__ int   d_cnt[MAXN];
__device__ int   d_cursor[MAXN];
__device__ int   d_offs[MAXN];
__device__ int   d_bsum[1024];
__device__ float d_dinv[MAXN];
__device__ int   d_src[MAXE];
__device__ float d_s1 [(size_t)MAXN * 16];   // dinv_j * (x @ W1)
__device__ float d_h1 [(size_t)MAXN * 16];   // relu(layer1 out)
__device__ float d_s2 [(size_t)MAXN * 32];   // dinv_j * (h1 @ W2)
__device__ float d_gsum[NUM_G * 32];
__device__ int   d_gcnt[NUM_G];

// ---------------- init ----------------
__global__ void k_zero(int n) {
    int i = blockIdx.x * blockDim.x + threadIdx.x;
    if (i < n) { d_cnt[i] = 0; d_cursor[i] = 0; }
    if (i < NUM_G * 32) d_gsum[i] = 0.0f;
    if (i < NUM_G) d_gcnt[i] = 0;
}

// ---------------- degree count (targets = edge_index[1]), 4 edges/thread ---
__global__ void k_deg(const int* __restrict__ col, int E4) {
    int t = blockIdx.x * blockDim.x + threadIdx.x;
    if (t < E4) {
        int4 c = ((const int4*)col)[t];
        atomicAdd(&d_cnt[c.x], 1);
        atomicAdd(&d_cnt[c.y], 1);
        atomicAdd(&d_cnt[c.z], 1);
        atomicAdd(&d_cnt[c.w], 1);
    }
}

// ---------------- exclusive scan of cnt -> offs ----------------
__global__ void k_scan1(int n) {
    __shared__ int s[1024];
    int tid = threadIdx.x;
    int gid = blockIdx.x * 1024 + tid;
    int v = (gid < n) ? d_cnt[gid] : 0;
    s[tid] = v;
    __syncthreads();
    for (int d = 1; d < 1024; d <<= 1) {
        int t = (tid >= d) ? s[tid - d] : 0;
        __syncthreads();
        s[tid] += t;
        __syncthreads();
    }
    if (gid < n) d_offs[gid] = s[tid] - v;
    if (tid == 1023) d_bsum[blockIdx.x] = s[1023];
}

__global__ void k_scan2(int nb) {
    __shared__ int s[1024];
    int tid = threadIdx.x;
    int v = (tid < nb) ? d_bsum[tid] : 0;
    s[tid] = v;
    __syncthreads();
    for (int d = 1; d < 1024; d <<= 1) {
        int t = (tid >= d) ? s[tid - d] : 0;
        __syncthreads();
        s[tid] += t;
        __syncthreads();
    }
    if (tid < nb) d_bsum[tid] = s[tid] - v;
}

__global__ void k_scan3_dinv(int n) {
    int gid = blockIdx.x * 1024 + threadIdx.x;
    if (gid < n) {
        d_offs[gid] += d_bsum[blockIdx.x];
        d_dinv[gid] = rsqrtf((float)d_cnt[gid] + 1.0f);
    }
}

// ---------------- CSR fill, 4 edges/thread ----------------
__global__ void k_fill(const int* __restrict__ ei, int E, int E4) {
    int t = blockIdx.x * blockDim.x + threadIdx.x;
    if (t >= E4) return;
    int4 r = ((const int4*)ei)[t];
    int4 c = ((const int4*)(ei + E))[t];
    d_src[d_offs[c.x] + atomicAdd(&d_cursor[c.x], 1)] = r.x;
    d_src[d_offs[c.y] + atomicAdd(&d_cursor[c.y], 1)] = r.y;
    d_src[d_offs[c.z] + atomicAdd(&d_cursor[c.z], 1)] = r.z;
    d_src[d_offs[c.w] + atomicAdd(&d_cursor[c.w], 1)] = r.w;
}

// ------------- s1 = dinv * (x @ W1)  (3 -> 16), prescaled -------------
__global__ void k_xw1(const float* __restrict__ x, const float* __restrict__ W1, int n) {
    __shared__ float w[48];
    if (threadIdx.x < 48) w[threadIdx.x] = W1[threadIdx.x];
    __syncthreads();
    int i = blockIdx.x * blockDim.x + threadIdx.x;
    if (i >= n) return;
    float x0 = x[3 * (size_t)i], x1 = x[3 * (size_t)i + 1], x2 = x[3 * (size_t)i + 2];
    float di = d_dinv[i];
    float4* out = (float4*)(d_s1 + (size_t)i * 16);
#pragma unroll
    for (int q = 0; q < 4; q++) {
        float4 v;
        v.x = di * (x0 * w[4*q+0] + x1 * w[16+4*q+0] + x2 * w[32+4*q+0]);
        v.y = di * (x0 * w[4*q+1] + x1 * w[16+4*q+1] + x2 * w[32+4*q+1]);
        v.z = di * (x0 * w[4*q+2] + x1 * w[16+4*q+2] + x2 * w[32+4*q+2]);
        v.w = di * (x0 * w[4*q+3] + x1 * w[16+4*q+3] + x2 * w[32+4*q+3]);
        out[q] = v;
    }
}

// ------- aggregation layer 1 (F=16): warp/node, lane = e8 x f4 -------
__global__ void k_agg1(const float* __restrict__ b1, int n) {
    int w = (blockIdx.x * blockDim.x + threadIdx.x) >> 5;
    if (w >= n) return;
    int lane = threadIdx.x & 31;
    int f = lane & 3;        // feature chunk (float4)
    int e = lane >> 2;       // edge subgroup 0..7

    int o = d_offs[w];
    int cnt = d_cnt[w];
    float4 acc = make_float4(0.f, 0.f, 0.f, 0.f);
    for (int base = 0; base < cnt; base += 8) {
        int k = base + e;
        if (k < cnt) {
            int j = __ldg(&d_src[o + k]);
            float4 v = ((const float4*)(d_s1 + (size_t)j * 16))[f];
            acc.x += v.x; acc.y += v.y; acc.z += v.z; acc.w += v.w;
        }
    }
#pragma unroll
    for (int off = 16; off >= 4; off >>= 1) {
        acc.x += __shfl_xor_sync(0xffffffffu, acc.x, off);
        acc.y += __shfl_xor_sync(0xffffffffu, acc.y, off);
        acc.z += __shfl_xor_sync(0xffffffffu, acc.z, off);
        acc.w += __shfl_xor_sync(0xffffffffu, acc.w, off);
    }
    if (lane < 4) {
        float di = d_dinv[w];
        float4 self = ((const float4*)(d_s1 + (size_t)w * 16))[f];
        float4 hv;
        hv.x = fmaxf(di * (acc.x + self.x) + b1[4*f+0], 0.f);
        hv.y = fmaxf(di * (acc.y + self.y) + b1[4*f+1], 0.f);
        hv.z = fmaxf(di * (acc.z + self.z) + b1[4*f+2], 0.f);
        hv.w = fmaxf(di * (acc.w + self.w) + b1[4*f+3], 0.f);
        ((float4*)(d_h1 + (size_t)w * 16))[f] = hv;
    }
}

// ------------- s2 = dinv * (h1 @ W2)  (16 -> 32), prescaled -------------
__global__ void k_xw2(const float* __restrict__ W2, int n) {
    __shared__ float w[512];
    for (int t = threadIdx.x; t < 512; t += blockDim.x) w[t] = W2[t];
    __syncthreads();
    int i = blockIdx.x * blockDim.x + threadIdx.x;
    if (i >= n) return;
    float h[16];
    const float4* hin = (const float4*)(d_h1 + (size_t)i * 16);
#pragma unroll
    for (int q = 0; q < 4; q++) {
        float4 v = hin[q];
        h[4*q] = v.x; h[4*q+1] = v.y; h[4*q+2] = v.z; h[4*q+3] = v.w;
    }
    float di = d_dinv[i];
    float4* out = (float4*)(d_s2 + (size_t)i * 32);
#pragma unroll
    for (int q = 0; q < 8; q++) {
        float4 v;
        float s0 = 0.f, s1 = 0.f, s2 = 0.f, s3 = 0.f;
#pragma unroll
        for (int k = 0; k < 16; k++) {
            const float* wr = w + k * 32 + 4 * q;
            s0 += h[k] * wr[0];
            s1 += h[k] * wr[1];
            s2 += h[k] * wr[2];
            s3 += h[k] * wr[3];
        }
        v.x = di * s0; v.y = di * s1; v.z = di * s2; v.w = di * s3;
        out[q] = v;
    }
}

// --- aggregation layer 2 (F=32): warp/node, lane = e4 x f8, fused pool ---
__global__ void k_agg2(const float* __restrict__ b2,
                       const int* __restrict__ batch, int n) {
    int w = (blockIdx.x * blockDim.x + threadIdx.x) >> 5;
    if (w >= n) return;
    int lane = threadIdx.x & 31;
    int f = lane & 7;        // feature chunk (float4) 0..7
    int e = lane >> 3;       // edge subgroup 0..3

    int o = d_offs[w];
    int cnt = d_cnt[w];
    float4 acc = make_float4(0.f, 0.f, 0.f, 0.f);
    for (int base = 0; base < cnt; base += 4) {
        int k = base + e;
        if (k < cnt) {
            int j = __ldg(&d_src[o + k]);
            float4 v = ((const float4*)(d_s2 + (size_t)j * 32))[f];
            acc.x += v.x; acc.y += v.y; acc.z += v.z; acc.w += v.w;
        }
    }
#pragma unroll
    for (int off = 16; off >= 8; off >>= 1) {
        acc.x += __shfl_xor_sync(0xffffffffu, acc.x, off);
        acc.y += __shfl_xor_sync(0xffffffffu, acc.y, off);
        acc.z += __shfl_xor_sync(0xffffffffu, acc.z, off);
        acc.w += __shfl_xor_sync(0xffffffffu, acc.w, off);
    }
    if (lane < 8) {
        float di = d_dinv[w];
        float4 self = ((const float4*)(d_s2 + (size_t)w * 32))[f];
        int g = batch[w];
        float* gs = d_gsum + g * 32 + 4 * f;
        float h0 = fmaxf(di * (acc.x + self.x) + b2[4*f+0], 0.f);
        float h1 = fmaxf(di * (acc.y + self.y) + b2[4*f+1], 0.f);
        float h2 = fmaxf(di * (acc.z + self.z) + b2[4*f+2], 0.f);
        float h3 = fmaxf(di * (acc.w + self.w) + b2[4*f+3], 0.f);
        atomicAdd(&gs[0], h0);
        atomicAdd(&gs[1], h1);
        atomicAdd(&gs[2], h2);
        atomicAdd(&gs[3], h3);
        if (lane == 0) atomicAdd(&d_gcnt[g], 1);
    }
}

// ---------------- mean + FC + log_softmax ----------------
__global__ void k_final(const float* __restrict__ Wfc, const float* __restrict__ bfc,
                        float* __restrict__ out) {
    int g = blockIdx.x * blockDim.x + threadIdx.x;
    if (g >= NUM_G) return;
    float c = (float)d_gcnt[g];
    float inv = 1.0f / fmaxf(c, 1.0f);
    float l0 = bfc[0], l1 = bfc[1];
    const float* gs = d_gsum + g * 32;
#pragma unroll
    for (int k = 0; k < 32; k++) {
        float m = gs[k] * inv;
        l0 += m * Wfc[k * 2 + 0];
        l1 += m * Wfc[k * 2 + 1];
    }
    float mx = fmaxf(l0, l1);
    float lse = mx + logf(expf(l0 - mx) + expf(l1 - mx));
    out[g * 2 + 0] = l0 - lse;
    out[g * 2 + 1] = l1 - lse;
}

// ---------------- launch ----------------
extern "C" void kernel_launch(void* const* d_in, const int* in_sizes, int n_in,
                              void* d_out, int out_size) {
    const float* x   = (const float*)d_in[0];
    const int*   ei  = (const int*)d_in[1];
    const int*   bat = (const int*)d_in[2];
    const float* W1  = (const float*)d_in[3];
    const float* b1  = (const float*)d_in[4];
    const float* W2  = (const float*)d_in[5];
    const float* b2  = (const float*)d_in[6];
    const float* Wfc = (const float*)d_in[7];
    const float* bfc = (const float*)d_in[8];
    float* out = (float*)d_out;

    int N = in_sizes[0] / 3;
    int E = in_sizes[1] / 2;
    int E4 = E / 4;   // E = 6.4M, divisible by 4

    int zmax = N > NUM_G * 32 ? N : NUM_G * 32;
    k_zero<<<(zmax + 255) / 256, 256>>>(N);
    k_deg<<<(E4 + 255) / 256, 256>>>(ei + E, E4);

    int nb = (N + 1023) / 1024;
    k_scan1<<<nb, 1024>>>(N);
    k_scan2<<<1, 1024>>>(nb);
    k_scan3_dinv<<<nb, 1024>>>(N);

    k_fill<<<(E4 + 255) / 256, 256>>>(ei, E, E4);

    k_xw1<<<(N + 255) / 256, 256>>>(x, W1, N);
    k_agg1<<<(N + 7) / 8, 256>>>(b1, N);
    k_xw2<<<(N + 255) / 256, 256>>>(W2, N);
    k_agg2<<<(N + 7) / 8, 256>>>(b2, bat, N);
    k_final<<<(NUM_G + 255) / 256, 256>>>(Wfc, bfc, out);
}

// round 4
// speedup vs baseline: 2.8993x; 1.0791x over previous
#include <cuda_runtime.h>

#define MAXN 200000
#define MAXE 6400000
#define NUM_G 1024

// ---------------- scratch ----------------
__device__ int   d_cnt[MAXN];
__device__ int   d_offs[MAXN];    // after k_fill: offs[i] = END of row i
__device__ int   d_bsum[1024];
__device__ float d_dinv[MAXN];
__device__ int   d_src[MAXE];
__device__ float d_s1[(size_t)MAXN * 4];    // dinv_j * x_j  (float4-padded)
__device__ float d_s2[(size_t)MAXN * 16];   // dinv_j * h1_j
__device__ float d_gsum[NUM_G * 32];
__device__ int   d_gcnt[NUM_G];

// ---------------- init ----------------
__global__ void k_zero(int n) {
    int i = blockIdx.x * blockDim.x + threadIdx.x;
    if (i < n) d_cnt[i] = 0;
    if (i < NUM_G * 32) d_gsum[i] = 0.0f;
    if (i < NUM_G) d_gcnt[i] = 0;
}

// ---------------- degree count (targets = edge_index[1]), 4 edges/thread ---
__global__ void k_deg(const int* __restrict__ col, int E4) {
    int t = blockIdx.x * blockDim.x + threadIdx.x;
    if (t < E4) {
        int4 c = ((const int4*)col)[t];
        atomicAdd(&d_cnt[c.x], 1);
        atomicAdd(&d_cnt[c.y], 1);
        atomicAdd(&d_cnt[c.z], 1);
        atomicAdd(&d_cnt[c.w], 1);
    }
}

// ---------------- exclusive scan of cnt -> offs ----------------
__global__ void k_scan1(int n) {
    __shared__ int s[1024];
    int tid = threadIdx.x;
    int gid = blockIdx.x * 1024 + tid;
    int v = (gid < n) ? d_cnt[gid] : 0;
    s[tid] = v;
    __syncthreads();
    for (int d = 1; d < 1024; d <<= 1) {
        int t = (tid >= d) ? s[tid - d] : 0;
        __syncthreads();
        s[tid] += t;
        __syncthreads();
    }
    if (gid < n) d_offs[gid] = s[tid] - v;
    if (tid == 1023) d_bsum[blockIdx.x] = s[1023];
}

__global__ void k_scan2(int nb) {
    __shared__ int s[1024];
    int tid = threadIdx.x;
    int v = (tid < nb) ? d_bsum[tid] : 0;
    s[tid] = v;
    __syncthreads();
    for (int d = 1; d < 1024; d <<= 1) {
        int t = (tid >= d) ? s[tid - d] : 0;
        __syncthreads();
        s[tid] += t;
        __syncthreads();
    }
    if (tid < nb) d_bsum[tid] = s[tid] - v;
}

// scan fixup + dinv + prescaled layer-1 features (s1 = dinv * x, padded)
__global__ void k_scan3(const float* __restrict__ x, int n) {
    int gid = blockIdx.x * 1024 + threadIdx.x;
    if (gid < n) {
        d_offs[gid] += d_bsum[blockIdx.x];
        float di = rsqrtf((float)d_cnt[gid] + 1.0f);
        d_dinv[gid] = di;
        float4 v;
        v.x = di * x[3 * (size_t)gid];
        v.y = di * x[3 * (size_t)gid + 1];
        v.z = di * x[3 * (size_t)gid + 2];
        v.w = 0.0f;
        ((float4*)d_s1)[gid] = v;
    }
}

// ---------------- CSR fill (bump d_offs itself; row end = offs) ----------
__global__ void k_fill(const int* __restrict__ ei, int E, int E4) {
    int t = blockIdx.x * blockDim.x + threadIdx.x;
    if (t >= E4) return;
    int4 r = ((const int4*)ei)[t];
    int4 c = ((const int4*)(ei + E))[t];
    d_src[atomicAdd(&d_offs[c.x], 1)] = r.x;
    d_src[atomicAdd(&d_offs[c.y], 1)] = r.y;
    d_src[atomicAdd(&d_offs[c.z], 1)] = r.z;
    d_src[atomicAdd(&d_offs[c.w], 1)] = r.w;
}

// ---- layer 1: aggregate 4-float rows, fused 3->16 transform + ReLU ----
// warp per node; lane = edge. After xor-reduce every lane holds the sum;
// lanes 0..15 compute feature f and write s2 = dinv * relu(...).
__global__ void k_agg1(const float* __restrict__ W1, const float* __restrict__ b1, int n) {
    int w = (blockIdx.x * blockDim.x + threadIdx.x) >> 5;
    if (w >= n) return;
    int lane = threadIdx.x & 31;

    int oe = d_offs[w];           // end of row
    int os = oe - d_cnt[w];       // start
    float ax = 0.f, ay = 0.f, az = 0.f;
    for (int k = os + lane; k < oe; k += 32) {
        int j = __ldg(&d_src[k]);
        float4 v = ((const float4*)d_s1)[j];
        ax += v.x; ay += v.y; az += v.z;
    }
#pragma unroll
    for (int off = 16; off; off >>= 1) {
        ax += __shfl_xor_sync(0xffffffffu, ax, off);
        ay += __shfl_xor_sync(0xffffffffu, ay, off);
        az += __shfl_xor_sync(0xffffffffu, az, off);
    }
    float di = d_dinv[w];
    float4 self = ((const float4*)d_s1)[w];       // broadcast load
    float a0 = di * (ax + self.x);
    float a1 = di * (ay + self.y);
    float a2 = di * (az + self.z);
    if (lane < 16) {
        float h = a0 * __ldg(&W1[lane]) + a1 * __ldg(&W1[16 + lane])
                + a2 * __ldg(&W1[32 + lane]) + __ldg(&b1[lane]);
        h = fmaxf(h, 0.0f);
        d_s2[(size_t)w * 16 + lane] = di * h;
    }
}

// ---- layer 2: aggregate 16-float rows, fused 16->32 transform + ReLU
//      + global mean-pool scatter. warp per node; lane = e8 x f4. ----
__global__ void k_agg2(const float* __restrict__ W2, const float* __restrict__ b2,
                       const int* __restrict__ batch, int n) {
    __shared__ float w2s[512];
    for (int t = threadIdx.x; t < 512; t += blockDim.x) w2s[t] = W2[t];
    __syncthreads();

    int w = (blockIdx.x * blockDim.x + threadIdx.x) >> 5;
    if (w >= n) return;
    int lane = threadIdx.x & 31;
    int f = lane & 3;       // float4 chunk of the 16-float row
    int e = lane >> 2;      // edge subgroup 0..7

    int oe = d_offs[w];
    int os = oe - d_cnt[w];
    float4 acc = make_float4(0.f, 0.f, 0.f, 0.f);
    for (int k = os + e; k < oe; k += 8) {
        int j = __ldg(&d_src[k]);
        float4 v = ((const float4*)(d_s2 + (size_t)j * 16))[f];
        acc.x += v.x; acc.y += v.y; acc.z += v.z; acc.w += v.w;
    }
    if (e == 0) {  // self-loop term
        float4 v = ((const float4*)(d_s2 + (size_t)w * 16))[f];
        acc.x += v.x; acc.y += v.y; acc.z += v.z; acc.w += v.w;
    }
#pragma unroll
    for (int off = 4; off <= 16; off <<= 1) {
        acc.x += __shfl_xor_sync(0xffffffffu, acc.x, off);
        acc.y += __shfl_xor_sync(0xffffffffu, acc.y, off);
        acc.z += __shfl_xor_sync(0xffffffffu, acc.z, off);
        acc.w += __shfl_xor_sync(0xffffffffu, acc.w, off);
    }
    float di = d_dinv[w];
    acc.x *= di; acc.y *= di; acc.z *= di; acc.w *= di;

    // gather full 16-vector into every lane via shuffles
    float av[16];
#pragma unroll
    for (int q = 0; q < 4; q++) {
        int srcl = (lane & 28) | q;
        av[4 * q + 0] = __shfl_sync(0xffffffffu, acc.x, srcl);
        av[4 * q + 1] = __shfl_sync(0xffffffffu, acc.y, srcl);
        av[4 * q + 2] = __shfl_sync(0xffffffffu, acc.z, srcl);
        av[4 * q + 3] = __shfl_sync(0xffffffffu, acc.w, srcl);
    }
    // each lane computes output feature `lane`
    float o = __ldg(&b2[lane]);
#pragma unroll
    for (int k = 0; k < 16; k++) o += av[k] * w2s[k * 32 + lane];
    o = fmaxf(o, 0.0f);

    int g = batch[w];
    atomicAdd(&d_gsum[g * 32 + lane], o);
    if (lane == 0) atomicAdd(&d_gcnt[g], 1);
}

// ---------------- mean + FC + log_softmax ----------------
__global__ void k_final(const float* __restrict__ Wfc, const float* __restrict__ bfc,
                        float* __restrict__ out) {
    int g = blockIdx.x * blockDim.x + threadIdx.x;
    if (g >= NUM_G) return;
    float c = (float)d_gcnt[g];
    float inv = 1.0f / fmaxf(c, 1.0f);
    float l0 = bfc[0], l1 = bfc[1];
    const float* gs = d_gsum + g * 32;
#pragma unroll
    for (int k = 0; k < 32; k++) {
        float m = gs[k] * inv;
        l0 += m * Wfc[k * 2 + 0];
        l1 += m * Wfc[k * 2 + 1];
    }
    float mx = fmaxf(l0, l1);
    float lse = mx + logf(expf(l0 - mx) + expf(l1 - mx));
    out[g * 2 + 0] = l0 - lse;
    out[g * 2 + 1] = l1 - lse;
}

// ---------------- launch ----------------
extern "C" void kernel_launch(void* const* d_in, const int* in_sizes, int n_in,
                              void* d_out, int out_size) {
    const float* x   = (const float*)d_in[0];
    const int*   ei  = (const int*)d_in[1];
    const int*   bat = (const int*)d_in[2];
    const float* W1  = (const float*)d_in[3];
    const float* b1  = (const float*)d_in[4];
    const float* W2  = (const float*)d_in[5];
    const float* b2  = (const float*)d_in[6];
    const float* Wfc = (const float*)d_in[7];
    const float* bfc = (const float*)d_in[8];
    float* out = (float*)d_out;

    int N = in_sizes[0] / 3;
    int E = in_sizes[1] / 2;
    int E4 = E / 4;

    int zmax = N > NUM_G * 32 ? N : NUM_G * 32;
    k_zero<<<(zmax + 255) / 256, 256>>>(N);
    k_deg<<<(E4 + 255) / 256, 256>>>(ei + E, E4);

    int nb = (N + 1023) / 1024;
    k_scan1<<<nb, 1024>>>(N);
    k_scan2<<<1, 1024>>>(nb);
    k_scan3<<<nb, 1024>>>(x, N);

    k_fill<<<(E4 + 255) / 256, 256>>>(ei, E, E4);

    k_agg1<<<(N + 7) / 8, 256>>>(W1, b1, N);
    k_agg2<<<(N + 7) / 8, 256>>>(W2, b2, bat, N);
    k_final<<<(NUM_G + 255) / 256, 256>>>(Wfc, bfc, out);
}